// round 12
// baseline (speedup 1.0000x reference)
#include <cuda_runtime.h>
#include <cuda_fp16.h>
#include <math.h>

// ---------------- static problem config ----------------
#define BN      960
#define P       144
#define DIM     192
#define HEADS   6
#define DH      32
#define WT      64
#define MW      15
#define PSQ     (P * P)
#define M_TOT   (BN * P)          // 138240
#define SCALE   0.1767766952966369f
#define LOG2E   1.4426950408889634f

// ---------------- scratch ----------------
__device__ unsigned g_xo_h[(size_t)M_TOT * DIM / 2];                // 53 MB (attn out)
__device__ unsigned g_wq_h[(size_t)HEADS * 96 * 192 / 2];           // [h][n'=part*32+d][k]
__device__ unsigned g_wp_h[192 * 192 / 2];                          // [n][k]
__device__ unsigned g_bias_h[(size_t)WT * HEADS * PSQ / 2];         // 16 MB

// ---------------- helpers ----------------
__device__ __forceinline__ unsigned ph2(float a, float b) {
    __half2 h = __floats2half2_rn(a, b);
    return *(unsigned*)&h;
}
__device__ __forceinline__ unsigned ex2_h2(float a, float b) {
    unsigned p = ph2(a, b), y;
    asm("ex2.approx.f16x2 %0, %1;" : "=r"(y) : "r"(p));
    return y;
}
__device__ __forceinline__ void mma_f16(float c[4], const unsigned a[4], const unsigned b[2]) {
    asm volatile(
        "mma.sync.aligned.m16n8k16.row.col.f32.f16.f16.f32 "
        "{%0,%1,%2,%3}, {%4,%5,%6,%7}, {%8,%9}, {%0,%1,%2,%3};"
        : "+f"(c[0]), "+f"(c[1]), "+f"(c[2]), "+f"(c[3])
        : "r"(a[0]), "r"(a[1]), "r"(a[2]), "r"(a[3]), "r"(b[0]), "r"(b[1]));
}
__device__ __forceinline__ void ldsm4(unsigned r[4], unsigned saddr) {
    asm volatile("ldmatrix.sync.aligned.m8n8.x4.shared.b16 {%0,%1,%2,%3}, [%4];"
                 : "=r"(r[0]), "=r"(r[1]), "=r"(r[2]), "=r"(r[3]) : "r"(saddr));
}
__device__ __forceinline__ void cp_async16(void* smem, const void* gmem) {
    unsigned s = (unsigned)__cvta_generic_to_shared(smem);
    asm volatile("cp.async.ca.shared.global [%0], [%1], 16;" :: "r"(s), "l"(gmem));
}
#define CP_COMMIT() asm volatile("cp.async.commit_group;")
template<int N> __device__ __forceinline__ void cp_wait() {
    asm volatile("cp.async.wait_group %0;" :: "n"(N));
}

// ---------------- fused prep: bias densify + weight reshape ----------------
#define NB_B 2592                 // WT * PSQ/2 / 256
#define NB_W2 288                 // (6*96*96 + 192*96) / 256
#define NB_TOT (NB_B + NB_W2)

__global__ void __launch_bounds__(256) prep_all(
    const float* __restrict__ wq, const float* __restrict__ wp,
    const float* __restrict__ table) {
    const int b = blockIdx.x;
    if (b < NB_B) {
        const int id = b * 256 + threadIdx.x;
        const int wt = id / (PSQ / 2), jp = id % (PSQ / 2);
        const int ij0 = 2 * jp;
        const int i = ij0 / P, j0 = ij0 % P;
        const int zi = i / 72, hi_ = (i / 12) % 6, wi = i % 12;
        const int rowterm = zi * 828 + hi_ * 23 + wi + 11;
        const int j1 = j0 + 1;
        const int pos0 = rowterm + (j0 / 72) * 1656 + ((j0 / 12) % 6) * 138 - (j0 % 12);
        const int pos1 = rowterm + (j1 / 72) * 1656 + ((j1 / 12) % 6) * 138 - (j1 % 12);
        const float* s0 = table + (size_t)pos0 * (WT * HEADS) + wt * HEADS;
        const float* s1 = table + (size_t)pos1 * (WT * HEADS) + wt * HEADS;
        unsigned* dst = g_bias_h + (size_t)wt * HEADS * (PSQ / 2) + jp;
#pragma unroll
        for (int h = 0; h < HEADS; h++)
            dst[(size_t)h * (PSQ / 2)] = ph2(__ldg(s0 + h) * LOG2E, __ldg(s1 + h) * LOG2E);
    } else {
        const int id = (b - NB_B) * 256 + threadIdx.x;
        if (id < HEADS * 96 * 96) {
            // wqkv -> [h][n'=part*32+d][k] halfs, Q part scaled by SCALE*LOG2E
            const int h = id / (96 * 96), rem = id % (96 * 96);
            const int np = rem / 96, kp = rem % 96, k = kp * 2;
            const int ng = (np / 32) * 192 + h * 32 + (np % 32);
            float v0 = wq[(size_t)k * 576 + ng];
            float v1 = wq[(size_t)(k + 1) * 576 + ng];
            if (np < 32) { v0 *= SCALE * LOG2E; v1 *= SCALE * LOG2E; }
            g_wq_h[(size_t)(h * 96 + np) * 96 + kp] = ph2(v0, v1);
        } else {
            const int id2 = id - HEADS * 96 * 96;   // < 192*96
            const int n = id2 / 96, kp = id2 % 96, k = kp * 2;
            g_wp_h[n * 96 + kp] = ph2(wp[(size_t)k * 192 + n], wp[(size_t)(k + 1) * 192 + n]);
        }
    }
}

// ---------------- fused QKV + attention: one CTA per window ----------------
// smem: xs[144][200]h, wslab[96][200]h, ks[144][40]h, vT[32][152]h
#define XS_STR 200
#define W_STR  200
#define XS_OFF 0
#define W_OFF  (144 * XS_STR)
#define KS_OFF (W_OFF + 96 * W_STR)
#define VT_OFF (KS_OFF + 144 * 40)
#define FUSED_SMEM_H (VT_OFF + 32 * 152)     // halfs

__global__ void __launch_bounds__(288, 1) attn_fused(
    const float* __restrict__ x, const float* __restrict__ mask) {
    extern __shared__ __half smh[];
    __half* xs    = smh + XS_OFF;
    __half* wslab = smh + W_OFF;
    __half* ks    = smh + KS_OFF;
    __half* vT    = smh + VT_OFF;

    const int bn = blockIdx.x;
    const int wt = bn / MW;
    const int tid = threadIdx.x;
    const int w = tid >> 5, lane = tid & 31;
    const int g = lane >> 2, t = lane & 3;
    const int wr = w * 16;

    const unsigned sXS = (unsigned)__cvta_generic_to_shared(xs);
    const unsigned sW  = (unsigned)__cvta_generic_to_shared(wslab);
    const unsigned sK  = (unsigned)__cvta_generic_to_shared(ks);
    const unsigned sV  = (unsigned)__cvta_generic_to_shared(vT);

    // ---- issue weight slab for head 0 ----
    const __half* wqh = (const __half*)g_wq_h;
#pragma unroll
    for (int j = 0; j < 8; j++) {
        const int idx = tid + 288 * j;          // 2304 chunks
        const int r = idx / 24, c = idx % 24;
        cp_async16(wslab + r * W_STR + c * 8, wqh + (size_t)r * 192 + c * 8);
    }
    CP_COMMIT();

    // ---- load + convert x window into xs ----
    {
        const float* xw = x + (size_t)bn * P * DIM;
        for (int f = tid; f < P * DIM / 4; f += 288) {
            const int p = f / 48, c4 = (f % 48) * 4;
            float4 v = *(const float4*)(xw + p * DIM + c4);
            uint2 o;
            o.x = ph2(v.x, v.y);
            o.y = ph2(v.z, v.w);
            *(uint2*)(xs + p * XS_STR + c4) = o;
        }
    }

    // ldmatrix lane geometry
    const int arow = wr + (lane & 15);
    const int acol = (lane >> 4) * 8;
    const int brow = (lane >> 4) * 8 + (lane & 7);
    const int bcol = ((lane >> 3) & 1) * 8;

    const __half* gbias = (const __half*)g_bias_h + (size_t)wt * HEADS * PSQ;
    const float* mk = mask + (size_t)bn * PSQ;
    __half* go_base = (__half*)g_xo_h + (size_t)bn * P * DIM;

    for (int h = 0; h < HEADS; h++) {
        cp_wait<0>();
        __syncthreads();   // wslab(h) ready; xs ready; ks/vT free from prev head

        // ---- QKV mini-GEMM: warp w computes rows wr..wr+16, all 96 cols ----
        float cq[4][4] = {}, ck[4][4] = {}, cv[4][4] = {};
#pragma unroll
        for (int kc = 0; kc < 12; kc++) {
            const int kk = kc * 16;
            unsigned af[4];
            ldsm4(af, sXS + (arow * XS_STR + kk + acol) * 2);
#pragma unroll
            for (int nt2 = 0; nt2 < 6; nt2++) {
                unsigned r[4];
                ldsm4(r, sW + ((brow + nt2 * 16) * W_STR + kk + bcol) * 2);
                unsigned b0[2] = { r[0], r[1] };
                unsigned b1[2] = { r[2], r[3] };
                float* c0;
                float* c1;
                if (nt2 < 2)      { c0 = cq[2 * nt2];     c1 = cq[2 * nt2 + 1]; }
                else if (nt2 < 4) { c0 = ck[2 * (nt2-2)]; c1 = ck[2 * (nt2-2) + 1]; }
                else              { c0 = cv[2 * (nt2-4)]; c1 = cv[2 * (nt2-4) + 1]; }
                mma_f16(c0, af, b0);
                mma_f16(c1, af, b1);
            }
        }

        // ---- epilogue: Q -> regs (A-frags), K -> ks, V -> vT ----
        unsigned aq[2][4];
#pragma unroll
        for (int kc = 0; kc < 2; kc++) {
            aq[kc][0] = ph2(cq[2 * kc][0], cq[2 * kc][1]);
            aq[kc][1] = ph2(cq[2 * kc][2], cq[2 * kc][3]);
            aq[kc][2] = ph2(cq[2 * kc + 1][0], cq[2 * kc + 1][1]);
            aq[kc][3] = ph2(cq[2 * kc + 1][2], cq[2 * kc + 1][3]);
        }
#pragma unroll
        for (int kt = 0; kt < 4; kt++) {
            const int d = kt * 8 + 2 * t;
            *(unsigned*)(ks + (wr + g) * 40 + d)     = ph2(ck[kt][0], ck[kt][1]);
            *(unsigned*)(ks + (wr + g + 8) * 40 + d) = ph2(ck[kt][2], ck[kt][3]);
        }
#pragma unroll
        for (int vt = 0; vt < 4; vt++) {
            const int d = vt * 8 + 2 * t;
            vT[d * 152 + wr + g]           = __float2half(cv[vt][0]);
            vT[(d + 1) * 152 + wr + g]     = __float2half(cv[vt][1]);
            vT[d * 152 + wr + g + 8]       = __float2half(cv[vt][2]);
            vT[(d + 1) * 152 + wr + g + 8] = __float2half(cv[vt][3]);
        }
        __syncthreads();   // K/V visible; wslab reads done

        // ---- prefetch next head's weight slab (overlaps attention) ----
        if (h < HEADS - 1) {
#pragma unroll
            for (int j = 0; j < 8; j++) {
                const int idx = tid + 288 * j;
                const int r = idx / 24, c = idx % 24;
                cp_async16(wslab + r * W_STR + c * 8,
                           wqh + (size_t)((h + 1) * 96 + r) * 192 + c * 8);
            }
            CP_COMMIT();
        }

        // ---- S = Q @ K^T ----
        float s[18][4] = {};
        const int krow = (lane >> 4) * 8 + (lane & 7);
        const int kcol = ((lane >> 3) & 1) * 8;
#pragma unroll
        for (int kc = 0; kc < 2; kc++) {
#pragma unroll
            for (int nt2 = 0; nt2 < 9; nt2++) {
                unsigned r[4];
                ldsm4(r, sK + ((krow + nt2 * 16) * 40 + kc * 16 + kcol) * 2);
                unsigned b0[2] = { r[0], r[1] };
                unsigned b1[2] = { r[2], r[3] };
                mma_f16(s[2 * nt2], aq[kc], b0);
                mma_f16(s[2 * nt2 + 1], aq[kc], b1);
            }
        }

        // ---- + bias(fp16, pre-log2e) + mask(fp32)*log2e ----
        {
            const __half* gb = gbias + (size_t)h * PSQ;
            const int r0 = wr + g, r1 = r0 + 8;
#pragma unroll
            for (int nt = 0; nt < 18; nt++) {
                const int c = nt * 8 + 2 * t;
                float2 b0 = __half22float2(*(const __half2*)(gb + (size_t)r0 * P + c));
                float2 b1 = __half22float2(*(const __half2*)(gb + (size_t)r1 * P + c));
                float2 m0 = *(const float2*)(mk + (size_t)r0 * P + c);
                float2 m1 = *(const float2*)(mk + (size_t)r1 * P + c);
                s[nt][0] += b0.x + m0.x * LOG2E;
                s[nt][1] += b0.y + m0.y * LOG2E;
                s[nt][2] += b1.x + m1.x * LOG2E;
                s[nt][3] += b1.y + m1.y * LOG2E;
            }
        }

        // ---- softmax: f16x2 ex2 -> AV A-frags ----
        unsigned pa[18], pb[18];
        float i0, i1;
        {
            float mx0 = -1e30f, mx1 = -1e30f;
#pragma unroll
            for (int nt = 0; nt < 18; nt++) {
                mx0 = fmaxf(mx0, fmaxf(s[nt][0], s[nt][1]));
                mx1 = fmaxf(mx1, fmaxf(s[nt][2], s[nt][3]));
            }
            mx0 = fmaxf(mx0, __shfl_xor_sync(0xffffffffu, mx0, 1));
            mx0 = fmaxf(mx0, __shfl_xor_sync(0xffffffffu, mx0, 2));
            mx1 = fmaxf(mx1, __shfl_xor_sync(0xffffffffu, mx1, 1));
            mx1 = fmaxf(mx1, __shfl_xor_sync(0xffffffffu, mx1, 2));
            float s0 = 0.f, s1 = 0.f;
#pragma unroll
            for (int nt = 0; nt < 18; nt++) {
                pa[nt] = ex2_h2(s[nt][0] - mx0, s[nt][1] - mx0);
                pb[nt] = ex2_h2(s[nt][2] - mx1, s[nt][3] - mx1);
                float2 fa = __half22float2(*(__half2*)&pa[nt]);
                float2 fb = __half22float2(*(__half2*)&pb[nt]);
                s0 += fa.x + fa.y;
                s1 += fb.x + fb.y;
            }
            s0 += __shfl_xor_sync(0xffffffffu, s0, 1);
            s0 += __shfl_xor_sync(0xffffffffu, s0, 2);
            s1 += __shfl_xor_sync(0xffffffffu, s1, 1);
            s1 += __shfl_xor_sync(0xffffffffu, s1, 2);
            i0 = 1.f / s0;
            i1 = 1.f / s1;
        }

        // ---- O = S @ V ----
        {
            float o[4][4] = {};
            const int vrow = (lane >> 4) * 8 + (lane & 7);
            const int vcol = ((lane >> 3) & 1) * 8;
#pragma unroll
            for (int kb = 0; kb < 9; kb++) {
                unsigned a[4];
                a[0] = pa[2 * kb];
                a[1] = pb[2 * kb];
                a[2] = pa[2 * kb + 1];
                a[3] = pb[2 * kb + 1];
#pragma unroll
                for (int nt2 = 0; nt2 < 2; nt2++) {
                    unsigned r[4];
                    ldsm4(r, sV + ((vrow + nt2 * 16) * 152 + kb * 16 + vcol) * 2);
                    unsigned b0[2] = { r[0], r[1] };
                    unsigned b1[2] = { r[2], r[3] };
                    mma_f16(o[nt2 * 2], a, b0);
                    mma_f16(o[nt2 * 2 + 1], a, b1);
                }
            }
            __half* go = go_base + h * 32;
#pragma unroll
            for (int nt = 0; nt < 4; nt++) {
                const int col = nt * 8 + 2 * t;
                *(unsigned*)(go + (size_t)(wr + g) * DIM + col)     = ph2(o[nt][0] * i0, o[nt][1] * i0);
                *(unsigned*)(go + (size_t)(wr + g + 8) * DIM + col) = ph2(o[nt][2] * i1, o[nt][3] * i1);
            }
        }
    }
}

// ---------------- fp16 mma proj GEMM (ldmatrix), 128x64 block tile ----------------
__global__ void __launch_bounds__(256) gemm_proj(const float* __restrict__ bias,
                                                 float* __restrict__ out) {
    extern __shared__ __half smh[];
    __half* As = smh;                    // [2][128*72]
    __half* Bs = smh + 2 * 128 * 72;     // [2][64*72]
    const __half* X = (const __half*)g_xo_h;
    const __half* W = (const __half*)g_wp_h;

    const int bm = blockIdx.y * 128, bn = blockIdx.x * 64;
    const int tid = threadIdx.x;
    const int w = tid >> 5, lane = tid & 31;
    const int g = lane >> 2, t = lane & 3;
    const int m0 = (w & 3) * 32, n0 = (w >> 2) * 32;

    const int arow = m0 + (lane & 15);
    const int acol = (lane >> 4) * 8;
    const int brow = n0 + (lane >> 4) * 8 + (lane & 7);
    const int bcol = ((lane >> 3) & 1) * 8;

    float cc[2][4][4] = {};

#define ISSUE_TILE(buf, k0)                                                       \
    {                                                                             \
        __half* Ab = As + (buf) * 128 * 72;                                       \
        _Pragma("unroll")                                                         \
        for (int i = 0; i < 4; i++) {                                             \
            const int idx = tid + 256 * i;                                        \
            const int r = idx >> 3, c = (idx & 7) * 8;                            \
            cp_async16(Ab + r * 72 + c, X + (size_t)(bm + r) * 192 + (k0) + c);   \
        }                                                                         \
        __half* Bb = Bs + (buf) * 64 * 72;                                        \
        _Pragma("unroll")                                                         \
        for (int i = 0; i < 2; i++) {                                             \
            const int idx = tid + 256 * i;                                        \
            const int r = idx >> 3, c = (idx & 7) * 8;                            \
            cp_async16(Bb + r * 72 + c, W + (size_t)(bn + r) * 192 + (k0) + c);   \
        }                                                                         \
    }

    ISSUE_TILE(0, 0);
    CP_COMMIT();

#pragma unroll
    for (int it = 0; it < 3; ++it) {
        if (it < 2) {
            ISSUE_TILE((it + 1) & 1, 64 * (it + 1));
            CP_COMMIT();
            cp_wait<1>();
        } else {
            cp_wait<0>();
        }
        __syncthreads();
        const unsigned sA = (unsigned)__cvta_generic_to_shared(As + (it & 1) * 128 * 72);
        const unsigned sB = (unsigned)__cvta_generic_to_shared(Bs + (it & 1) * 64 * 72);
#pragma unroll
        for (int kk = 0; kk < 64; kk += 16) {
            unsigned af[2][4], bf[4][2];
#pragma unroll
            for (int mt = 0; mt < 2; mt++)
                ldsm4(af[mt], sA + ((arow + mt * 16) * 72 + kk + acol) * 2);
#pragma unroll
            for (int nt2 = 0; nt2 < 2; nt2++) {
                unsigned r[4];
                ldsm4(r, sB + ((brow + nt2 * 16) * 72 + kk + bcol) * 2);
                bf[nt2 * 2][0] = r[0]; bf[nt2 * 2][1] = r[1];
                bf[nt2 * 2 + 1][0] = r[2]; bf[nt2 * 2 + 1][1] = r[3];
            }
#pragma unroll
            for (int mt = 0; mt < 2; mt++)
#pragma unroll
                for (int nt = 0; nt < 4; nt++)
                    mma_f16(cc[mt][nt], af[mt], bf[nt]);
        }
        __syncthreads();
    }
#undef ISSUE_TILE

#pragma unroll
    for (int mt = 0; mt < 2; mt++) {
#pragma unroll
        for (int half_ = 0; half_ < 2; half_++) {
            const int m = bm + m0 + mt * 16 + g + half_ * 8;
#pragma unroll
            for (int nt = 0; nt < 4; nt++) {
                const int n = bn + n0 + nt * 8 + 2 * t;
                float2 st;
                st.x = cc[mt][nt][half_ * 2 + 0] + __ldg(bias + n);
                st.y = cc[mt][nt][half_ * 2 + 1] + __ldg(bias + n + 1);
                *(float2*)(out + (size_t)m * DIM + n) = st;
            }
        }
    }
}

// ---------------- launcher ----------------
extern "C" void kernel_launch(void* const* d_in, const int* in_sizes, int n_in,
                              void* d_out, int out_size) {
    const float* x          = (const float*)d_in[0];
    const float* mask       = (const float*)d_in[1];
    const float* w_qkv      = (const float*)d_in[2];
    const float* w_proj     = (const float*)d_in[3];
    const float* b_proj     = (const float*)d_in[4];
    const float* bias_table = (const float*)d_in[5];
    float* out = (float*)d_out;

    const int smem_gemm = (2 * 128 * 72 + 2 * 64 * 72) * 2;   // 55296 B
    const int smem_fused = FUSED_SMEM_H * 2;                   // 117248 B
    cudaFuncSetAttribute(gemm_proj,
                         cudaFuncAttributeMaxDynamicSharedMemorySize, smem_gemm);
    cudaFuncSetAttribute(attn_fused,
                         cudaFuncAttributeMaxDynamicSharedMemorySize, smem_fused);

    prep_all<<<NB_TOT, 256>>>(w_qkv, w_proj, bias_table);
    attn_fused<<<BN, 288, smem_fused>>>(x, mask);
    gemm_proj<<<dim3(3, M_TOT / 128), 256, smem_gemm>>>(b_proj, out);
}